// round 6
// baseline (speedup 1.0000x reference)
#include <cuda_runtime.h>
#include <cuda_fp16.h>
#include <math.h>
#include <stdint.h>

#define N_NODES 768
#define WAV 6360
#define KPAD 6528       // 17 * 384
#define NCH 102         // KPAD / 64 chunks
#define HID 32
#define NH 4
#define GC 128
#define GC2 256
#define P_PATCH 8
#define SUP 96
#define NEG 0.2f

#define GSPLITS 17
#define CHUNK 384
#define KT 64
#define NSTG 6
#define MTILE 96

// device scratch (no allocation allowed)
__device__ float  d_Gp[GSPLITS * N_NODES * GC2];
__device__ float  d_G1[N_NODES * GC2];
__device__ float  d_G2[N_NODES * GC2];
__device__ float  d_z1[N_NODES * HID];
__device__ float  d_zh[N_NODES * HID];
__device__ float  d_es[NH * N_NODES * N_NODES];
__device__ __half d_Xi[N_NODES * NCH * 128];   // [m][chunk][64hi|64lo]
__device__ __half d_Wi[GC2 * NCH * 128];       // [n][chunk][64hi|64lo]

// ---------------------------------------------------------------------------
// PTX helpers (sm_90-level only; NO sm_100a features)
__device__ __forceinline__ uint32_t smem_u32(const void* p) {
    uint32_t a;
    asm("{ .reg .u64 t; cvta.to.shared.u64 t, %1; cvt.u32.u64 %0, t; }"
        : "=r"(a) : "l"(p));
    return a;
}
__device__ __forceinline__ void ldsm_x4(uint32_t* r, uint32_t a) {
    asm volatile("ldmatrix.sync.aligned.m8n8.x4.shared.b16 {%0,%1,%2,%3}, [%4];"
                 : "=r"(r[0]), "=r"(r[1]), "=r"(r[2]), "=r"(r[3]) : "r"(a));
}
__device__ __forceinline__ void mma_f16(float* c, const uint32_t* a, const uint32_t* b) {
    asm volatile("mma.sync.aligned.m16n8k16.row.col.f32.f16.f16.f32 "
                 "{%0,%1,%2,%3}, {%4,%5,%6,%7}, {%8,%9}, {%0,%1,%2,%3};"
                 : "+f"(c[0]), "+f"(c[1]), "+f"(c[2]), "+f"(c[3])
                 : "r"(a[0]), "r"(a[1]), "r"(a[2]), "r"(a[3]), "r"(b[0]), "r"(b[1]));
}
__device__ __forceinline__ void bulk_cp(uint32_t dst, const void* src, uint32_t bytes,
                                        uint32_t mbar) {
    asm volatile(
        "cp.async.bulk.shared::cluster.global.mbarrier::complete_tx::bytes "
        "[%0], [%1], %2, [%3];"
        :: "r"(dst), "l"(src), "r"(bytes), "r"(mbar) : "memory");
}
#define MBAR_INIT(a, n) \
    asm volatile("mbarrier.init.shared.b64 [%0], %1;" :: "r"(a), "r"(n) : "memory")
#define MBAR_INVAL(a) \
    asm volatile("mbarrier.inval.shared.b64 [%0];" :: "r"(a) : "memory")
#define MBAR_EXPECT(a, b) \
    asm volatile("mbarrier.arrive.expect_tx.shared.b64 _, [%0], %1;" \
                 :: "r"(a), "r"((uint32_t)(b)) : "memory")
#define FENCE_ASYNC() asm volatile("fence.proxy.async.shared::cta;" ::: "memory")

__device__ __forceinline__ void mbar_wait(uint32_t mbar, uint32_t parity) {
    uint32_t done;
    asm volatile("{\n\t.reg .pred p;\n\t"
                 "mbarrier.try_wait.parity.acquire.cta.shared::cta.b64 p, [%1], %2;\n\t"
                 "selp.b32 %0, 1, 0, p;\n\t}"
                 : "=r"(done) : "r"(mbar), "r"(parity) : "memory");
    if (!done) {
        asm volatile("{\n\t.reg .pred P1;\n\t"
                     "W1_%=:\n\t"
                     "mbarrier.try_wait.parity.acquire.cta.shared::cta.b64 P1, [%0], %1, 0x989680;\n\t"
                     "@P1 bra.uni W2_%=;\n\t"
                     "bra.uni W1_%=;\n\t"
                     "W2_%=:\n\t}"
                     :: "r"(mbar), "r"(parity) : "memory");
    }
}

// ---------------------------------------------------------------------------
// pre-split X: fp32 [768][6360] -> interleaved fp16 hi/lo chunks (zero pad)
__global__ void split_x(const float* __restrict__ X,
                        __half* __restrict__ Xi) {
    int k = blockIdx.x * 128 + threadIdx.x;
    int row = blockIdx.y;
    int c = k >> 6, p = k & 63;
    float v = (k < WAV) ? X[(size_t)row * WAV + k] : 0.f;
    __half h = __float2half_rn(v);
    size_t o = ((size_t)row * NCH + c) * 128 + p;
    Xi[o] = h;
    Xi[o + 64] = __float2half_rn(v - __half2float(h));
}

// pre-split + transpose W: [Wl|Wr][k][n] -> interleaved [n][chunk][64hi|64lo]
__global__ void split_wT(const float* __restrict__ Wl, const float* __restrict__ Wr,
                         __half* __restrict__ Wi) {
    __shared__ float t[32][33];
    int k0 = blockIdx.x * 32, n0 = blockIdx.y * 32;
    int tx = threadIdx.x, ty = threadIdx.y;   // 32 x 8
#pragma unroll
    for (int q = 0; q < 4; q++) {
        int ky = ty * 4 + q;
        int k = k0 + ky, n = n0 + tx;
        float v = 0.f;
        if (k < WAV)
            v = (n < GC) ? Wl[(size_t)k * GC + n] : Wr[(size_t)k * GC + (n - GC)];
        t[ky][tx] = v;
    }
    __syncthreads();
#pragma unroll
    for (int q = 0; q < 4; q++) {
        int ny = ty * 4 + q;
        int n = n0 + ny;
        int k = k0 + tx;
        float v = t[tx][ny];
        __half h = __float2half_rn(v);
        size_t o = ((size_t)n * NCH + (k >> 6)) * 128 + (k & 63);
        Wi[o] = h;
        Wi[o + 64] = __float2half_rn(v - __half2float(h));
    }
}

// ---------------------------------------------------------------------------
// bulk-copy pipelined fp16-split GEMM: Gp[s] = X @ W^T  (tile 96 x 256)
#define RSTR 272                        // smem row stride bytes (256 + 16)
#define ABYTES (MTILE * RSTR)           // 26112
#define BBYTES (256 * RSTR)             // 69632
#define STAGE (ABYTES + BBYTES)         // 95744
#define TXB ((MTILE + 256) * 256)       // 90112

__global__ void __launch_bounds__(256, 1)
gemm_bulk(const __half* __restrict__ Xi, const __half* __restrict__ Wi,
          float* __restrict__ Gp) {
    extern __shared__ char smem[];
    uint32_t tb = smem_u32(smem);
    uint32_t mbA = tb + 2 * STAGE;      // two 8B mbarriers

    int tid = threadIdx.x, lane = tid & 31, w = tid >> 5;
    int wm = w >> 2, wn = w & 3;        // 2 m-warps x 4 n-warps
    int m0 = blockIdx.x * MTILE;
    int s = blockIdx.y;

    if (tid == 0) { MBAR_INIT(mbA, 1); MBAR_INIT(mbA + 8, 1); }
    __syncthreads();

    auto issue = [&](int st) {
        int b = st & 1;
        int ci = s * NSTG + st;
        uint32_t mb = mbA + b * 8;
        if (tid == 0) MBAR_EXPECT(mb, TXB);
        for (int i = tid; i < MTILE + 256; i += 256) {
            uint32_t dst;
            const __half* src;
            if (i < MTILE) {
                dst = tb + b * STAGE + i * RSTR;
                src = Xi + ((size_t)(m0 + i) * NCH + ci) * 128;
            } else {
                int n = i - MTILE;
                dst = tb + b * STAGE + ABYTES + n * RSTR;
                src = Wi + ((size_t)n * NCH + ci) * 128;
            }
            bulk_cp(dst, src, 256, mb);
        }
    };

    float acc[3][8][4];
#pragma unroll
    for (int mt = 0; mt < 3; mt++)
#pragma unroll
        for (int nt = 0; nt < 8; nt++)
#pragma unroll
            for (int c = 0; c < 4; c++) acc[mt][nt][c] = 0.f;

    issue(0);
    issue(1);

    int l15 = lane & 15;
    uint32_t aColHi = ((lane >> 4) << 4);            // 0 / 16 bytes
    uint32_t bRowSel = ((lane >> 4) << 3) + (lane & 7);
    uint32_t bColSel = (((lane >> 3) & 1) << 4);

    for (int st = 0; st < NSTG; st++) {
        int b = st & 1;
        mbar_wait(mbA + b * 8, (st >> 1) & 1);

        uint32_t baseA = tb + b * STAGE;
        uint32_t baseB = baseA + ABYTES;
#pragma unroll
        for (int kk = 0; kk < 4; kk++) {             // 4 x k16
            uint32_t kb = kk * 32;
            uint32_t aH[3][4], aL[3][4];
#pragma unroll
            for (int mt = 0; mt < 3; mt++) {
                uint32_t ad = baseA + (wm * 48 + mt * 16 + l15) * RSTR + kb + aColHi;
                ldsm_x4(aH[mt], ad);
                ldsm_x4(aL[mt], ad + 128);
            }
#pragma unroll
            for (int p = 0; p < 4; p++) {
                uint32_t bd = baseB + (wn * 64 + p * 16 + bRowSel) * RSTR + kb + bColSel;
                uint32_t bh[4], bl[4];
                ldsm_x4(bh, bd);
                ldsm_x4(bl, bd + 128);
#pragma unroll
                for (int mt = 0; mt < 3; mt++) {
                    mma_f16(acc[mt][2 * p],     aH[mt], bh);
                    mma_f16(acc[mt][2 * p],     aH[mt], bl);
                    mma_f16(acc[mt][2 * p],     aL[mt], bh);
                    mma_f16(acc[mt][2 * p + 1], aH[mt], bh + 2);
                    mma_f16(acc[mt][2 * p + 1], aH[mt], bl + 2);
                    mma_f16(acc[mt][2 * p + 1], aL[mt], bh + 2);
                }
            }
        }
        __syncthreads();
        FENCE_ASYNC();
        if (st + 2 < NSTG) issue(st + 2);
    }

    // epilogue: split partials
    float* out = Gp + (size_t)s * N_NODES * GC2;
    int gid = lane >> 2, tig = lane & 3;
#pragma unroll
    for (int mt = 0; mt < 3; mt++) {
        int r = m0 + wm * 48 + mt * 16 + gid;
#pragma unroll
        for (int nt = 0; nt < 8; nt++) {
            int c = wn * 64 + nt * 8 + tig * 2;
            *(float2*)&out[(size_t)r * GC2 + c] =
                make_float2(acc[mt][nt][0], acc[mt][nt][1]);
            *(float2*)&out[(size_t)(r + 8) * GC2 + c] =
                make_float2(acc[mt][nt][2], acc[mt][nt][3]);
        }
    }
    __syncthreads();
    if (tid == 0) { MBAR_INVAL(mbA); MBAR_INVAL(mbA + 8); }
}

__global__ void reduce_split(const float* __restrict__ Gp, float* __restrict__ G) {
    int i = blockIdx.x * 256 + threadIdx.x;
    float s = 0.f;
#pragma unroll
    for (int p = 0; p < GSPLITS; p++) s += Gp[(size_t)p * (N_NODES * GC2) + i];
    G[i] = s;
}

// ---------------------------------------------------------------------------
// e[i,j,h] = sum_f a[f]*lrelu(gr[i,h,f]+gl[j,h,f]), masked -> es[h][i][j]
__global__ void e_kernel(const float* __restrict__ G,
                         const int* __restrict__ adj,
                         const float* __restrict__ avec,
                         float* __restrict__ es) {
    __shared__ float grs[32][33];
    __shared__ float gls[64][33];
    __shared__ float asm_[32];

    int i0 = blockIdx.x * 32, j0 = blockIdx.y * 64;
    int tid = threadIdx.x;
    int tj = tid & 15, ti = tid >> 4;

    if (tid < 32) asm_[tid] = avec[tid];

    int adjv[2][4];
#pragma unroll
    for (int r = 0; r < 2; r++)
#pragma unroll
        for (int q = 0; q < 4; q++)
            adjv[r][q] = adj[(size_t)(i0 + ti * 2 + r) * N_NODES + j0 + tj + 16 * q];

    for (int h = 0; h < NH; h++) {
        __syncthreads();
        {
            int r = tid >> 3, fq = (tid & 7) * 4;
            float4 v = *(const float4*)(G + (size_t)(i0 + r) * GC2 + GC + h * 32 + fq);
            grs[r][fq + 0] = v.x; grs[r][fq + 1] = v.y;
            grs[r][fq + 2] = v.z; grs[r][fq + 3] = v.w;
        }
#pragma unroll
        for (int e2 = 0; e2 < 2; e2++) {
            int slot = tid + e2 * 256;
            int r = slot >> 3, fq = (slot & 7) * 4;
            float4 v = *(const float4*)(G + (size_t)(j0 + r) * GC2 + h * 32 + fq);
            gls[r][fq + 0] = v.x; gls[r][fq + 1] = v.y;
            gls[r][fq + 2] = v.z; gls[r][fq + 3] = v.w;
        }
        __syncthreads();

        float acc[2][4];
#pragma unroll
        for (int r = 0; r < 2; r++)
#pragma unroll
            for (int q = 0; q < 4; q++) acc[r][q] = 0.f;

#pragma unroll
        for (int f = 0; f < 32; f++) {
            float av = asm_[f];
            float gr0 = grs[ti * 2][f];
            float gr1 = grs[ti * 2 + 1][f];
            float gl[4];
#pragma unroll
            for (int q = 0; q < 4; q++) gl[q] = gls[tj + 16 * q][f];
#pragma unroll
            for (int q = 0; q < 4; q++) {
                float s0 = gr0 + gl[q];
                float s1 = gr1 + gl[q];
                acc[0][q] = fmaf(av, fmaxf(s0, NEG * s0), acc[0][q]);
                acc[1][q] = fmaf(av, fmaxf(s1, NEG * s1), acc[1][q]);
            }
        }

        float* ep = es + (size_t)h * N_NODES * N_NODES;
#pragma unroll
        for (int r = 0; r < 2; r++) {
            float* row = ep + (size_t)(i0 + ti * 2 + r) * N_NODES + j0;
#pragma unroll
            for (int q = 0; q < 4; q++)
                row[tj + 16 * q] = adjv[r][q] ? acc[r][q] : -1e30f;
        }
    }
}

// ---------------------------------------------------------------------------
// softmax over j per (i,h); 256 threads, 2 warps per head.
__global__ void attw_kernel(const float* __restrict__ es,
                            float* __restrict__ attO) {
    __shared__ float pbuf[N_NODES * NH];
    __shared__ float wmax[8];
    __shared__ float wsum[8];
    int i = blockIdx.x;
    int tid = threadIdx.x;
    int lane = tid & 31, w = tid >> 5;
    int h = w >> 1, half = w & 1;

    const float* ep = es + ((size_t)h * N_NODES + i) * N_NODES + half * 384;
    float ev[12];
    float m = -1e30f;
#pragma unroll
    for (int k = 0; k < 12; k++) {
        ev[k] = ep[lane + 32 * k];
        m = fmaxf(m, ev[k]);
    }
#pragma unroll
    for (int o = 16; o > 0; o >>= 1)
        m = fmaxf(m, __shfl_xor_sync(0xffffffffu, m, o));
    if (lane == 0) wmax[w] = m;
    __syncthreads();
    float M = fmaxf(wmax[h * 2], wmax[h * 2 + 1]);

    float ss = 0.f;
#pragma unroll
    for (int k = 0; k < 12; k++) {
        ev[k] = expf(ev[k] - M);
        ss += ev[k];
    }
#pragma unroll
    for (int o = 16; o > 0; o >>= 1)
        ss += __shfl_xor_sync(0xffffffffu, ss, o);
    if (lane == 0) wsum[w] = ss;
    __syncthreads();
    float inv = 1.f / (wsum[h * 2] + wsum[h * 2 + 1]);

#pragma unroll
    for (int k = 0; k < 12; k++)
        pbuf[(half * 384 + lane + 32 * k) * NH + h] = ev[k] * inv;
    __syncthreads();

    float4* dst = (float4*)(attO + (size_t)i * N_NODES * NH);
    const float4* src = (const float4*)pbuf;
    for (int j = tid; j < N_NODES; j += 256) dst[j] = src[j];
}

// ---------------------------------------------------------------------------
// res: z[i,f] = 0.25 * sum_{j,h} att[i,j,h] * g_r[j,h,f]; 2-way j split
#define RT 6
__global__ void res_kernel(const float* __restrict__ G,
                           const float* __restrict__ attO,
                           float* __restrict__ outv, int doElu) {
    __shared__ float atts[2][RT][512];
    __shared__ float accsm[2][RT][GC];
    int i0 = blockIdx.x * RT;
    int tid = threadIdx.x;
    int half = tid >> 7, t = tid & 127;
    int h = t >> 5;

    float acc[RT];
#pragma unroll
    for (int it = 0; it < RT; it++) acc[it] = 0.f;

    for (int c = 0; c < 3; c++) {
        __syncthreads();
#pragma unroll
        for (int it = 0; it < RT; it++) {
            float4 v = *(const float4*)(attO + (size_t)(i0 + it) * (N_NODES * NH)
                                        + half * 1536 + c * 512 + t * 4);
            *(float4*)&atts[half][it][t * 4] = v;
        }
        __syncthreads();
#pragma unroll 4
        for (int jj = 0; jj < 128; jj++) {
            int j = half * 384 + c * 128 + jj;
            float g = G[(size_t)j * GC2 + GC + t];
#pragma unroll
            for (int it = 0; it < RT; it++)
                acc[it] = fmaf(atts[half][it][jj * NH + h], g, acc[it]);
        }
    }
#pragma unroll
    for (int it = 0; it < RT; it++) accsm[half][it][t] = acc[it];
    __syncthreads();

    if (tid < RT * 32) {
        int it = tid >> 5, f = tid & 31;
        float m = 0.f;
#pragma unroll
        for (int hh = 0; hh < 2; hh++)
#pragma unroll
            for (int q = 0; q < 4; q++)
                m += accsm[hh][it][q * 32 + f];
        m *= 0.25f;
        if (doElu) m = (m > 0.f) ? m : expm1f(m);
        outv[(size_t)(i0 + it) * HID + f] = m;
    }
}

// ---------------------------------------------------------------------------
__global__ void mapper_kernel(const float* __restrict__ z,
                              const float* __restrict__ Wm,
                              const float* __restrict__ bm,
                              float* __restrict__ staO,
                              float* __restrict__ zh) {
    __shared__ float ws[SUP * SUP];
    int p = blockIdx.x;
    int tid = threadIdx.x;
    for (int idx = tid; idx < SUP * SUP; idx += 256)
        ws[idx] = Wm[(size_t)p * SUP * SUP + idx];
    __syncthreads();

    for (int idx = tid; idx < SUP * HID; idx += 256) {
        int t = idx & 31, e = idx >> 5;
        float s = bm[p * SUP + e];
#pragma unroll 4
        for (int d = 0; d < SUP; d++)
            s = fmaf(z[(size_t)(p * SUP + d) * HID + t], ws[d * SUP + e], s);
        staO[(size_t)t * N_NODES + p * SUP + e] = s;
        zh[(size_t)(p * SUP + e) * HID + t] = s;
    }
}

__global__ void gemm_small(const float* __restrict__ zh,
                           const float* __restrict__ Wl,
                           const float* __restrict__ Wr,
                           float* __restrict__ G) {
    __shared__ float zr[HID];
    int i = blockIdx.x;
    int c = threadIdx.x;
    if (c < HID) zr[c] = zh[(size_t)i * HID + c];
    __syncthreads();
    const float* W = (c < GC) ? Wl : Wr;
    int cc = c & 127;
    float s = 0.f;
#pragma unroll
    for (int k = 0; k < HID; k++) s = fmaf(zr[k], W[k * GC + cc], s);
    G[(size_t)i * GC2 + c] = s;
}

// ---------------------------------------------------------------------------
extern "C" void kernel_launch(void* const* d_in, const int* in_sizes, int n_in,
                              void* d_out, int out_size) {
    const float* x    = (const float*)d_in[0];
    const float* Wl1  = (const float*)d_in[1];
    const float* Wr1  = (const float*)d_in[2];
    const float* a1   = (const float*)d_in[3];
    const float* Wm   = (const float*)d_in[4];
    const float* bm   = (const float*)d_in[5];
    const float* Wl2  = (const float*)d_in[6];
    const float* Wr2  = (const float*)d_in[7];
    const float* a2   = (const float*)d_in[8];
    const int*   adjS = (const int*)d_in[9];
    const int*   adjT = (const int*)d_in[10];

    float* out  = (float*)d_out;                           // [768,32]
    float* attS = out + N_NODES * HID;                     // [768,768,4]
    float* attT = attS + (size_t)N_NODES * N_NODES * NH;
    float* staO = attT + (size_t)N_NODES * N_NODES * NH;   // [32,768]

    float *gp, *g1, *g2, *z1, *zh, *es;
    __half *xi, *wi;
    cudaGetSymbolAddress((void**)&gp, d_Gp);
    cudaGetSymbolAddress((void**)&g1, d_G1);
    cudaGetSymbolAddress((void**)&g2, d_G2);
    cudaGetSymbolAddress((void**)&z1, d_z1);
    cudaGetSymbolAddress((void**)&zh, d_zh);
    cudaGetSymbolAddress((void**)&es, d_es);
    cudaGetSymbolAddress((void**)&xi, d_Xi);
    cudaGetSymbolAddress((void**)&wi, d_Wi);

    const int SMEM_GEMM = 2 * STAGE + 64;                  // 191552
    cudaFuncSetAttribute(gemm_bulk, cudaFuncAttributeMaxDynamicSharedMemorySize,
                         SMEM_GEMM);

    // pre-split inputs (interleaved hi/lo chunks)
    split_x<<<dim3(KPAD / 128, N_NODES), 128>>>(x, xi);
    split_wT<<<dim3(KPAD / 32, GC2 / 32), dim3(32, 8)>>>(Wl1, Wr1, wi);

    // layer 1
    gemm_bulk<<<dim3(N_NODES / MTILE, GSPLITS), 256, SMEM_GEMM>>>(xi, wi, gp);
    reduce_split<<<N_NODES * GC2 / 256, 256>>>(gp, g1);
    e_kernel<<<dim3(N_NODES / 32, N_NODES / 64), 256>>>(g1, adjS, a1, es);
    attw_kernel<<<N_NODES, 256>>>(es, attS);
    res_kernel<<<N_NODES / RT, 256>>>(g1, attS, z1, 1);

    // mapper
    mapper_kernel<<<P_PATCH, 256>>>(z1, Wm, bm, staO, zh);

    // layer 2
    gemm_small<<<N_NODES, 256>>>(zh, Wl2, Wr2, g2);
    e_kernel<<<dim3(N_NODES / 32, N_NODES / 64), 256>>>(g2, adjT, a2, es);
    attw_kernel<<<N_NODES, 256>>>(es, attT);
    res_kernel<<<N_NODES / RT, 256>>>(g2, attT, out, 0);
}

// round 7
// speedup vs baseline: 1.1507x; 1.1507x over previous
#include <cuda_runtime.h>
#include <cuda_fp16.h>
#include <math.h>
#include <stdint.h>

#define N_NODES 768
#define WAV 6360
#define HID 32
#define NH 4
#define GC 128          // H*HID
#define GC2 256         // [g_l | g_r]
#define P_PATCH 8
#define SUP 96
#define NEG 0.2f

#define GSPLITS 24
#define CHUNK 288       // 24*288 = 6912 >= 6360 (tail zero-filled)
#define NSTAGE 9        // CHUNK / 32
#define MTILE 128

// device scratch (no allocation allowed)
__device__ float  d_Gp[GSPLITS * N_NODES * GC2];
__device__ float  d_G1[N_NODES * GC2];
__device__ float  d_G2[N_NODES * GC2];
__device__ float  d_z1[N_NODES * HID];
__device__ float  d_zh[N_NODES * HID];
__device__ float  d_es[NH * N_NODES * N_NODES];   // e scores [h][i][j]
__device__ float  d_cr[N_NODES * NH];             // sum_f a_f * g_r
__device__ float  d_cl[N_NODES * NH];             // sum_f a_f * g_l
__device__ __half d_Wh[WAV * GC2];                // [Wl|Wr] hi halves
__device__ __half d_Wlo[WAV * GC2];               // lo halves

// ---------------------------------------------------------------------------
// PTX helpers (sm_90-level only)
__device__ __forceinline__ void ldsm_x4(uint32_t* r, uint32_t a) {
    asm volatile("ldmatrix.sync.aligned.m8n8.x4.shared.b16 {%0,%1,%2,%3}, [%4];"
                 : "=r"(r[0]), "=r"(r[1]), "=r"(r[2]), "=r"(r[3]) : "r"(a));
}
__device__ __forceinline__ void ldsm_x4t(uint32_t* r, uint32_t a) {
    asm volatile("ldmatrix.sync.aligned.m8n8.x4.trans.shared.b16 {%0,%1,%2,%3}, [%4];"
                 : "=r"(r[0]), "=r"(r[1]), "=r"(r[2]), "=r"(r[3]) : "r"(a));
}
__device__ __forceinline__ void mma_f16(float* c, const uint32_t* a, const uint32_t* b) {
    asm volatile("mma.sync.aligned.m16n8k16.row.col.f32.f16.f16.f32 "
                 "{%0,%1,%2,%3}, {%4,%5,%6,%7}, {%8,%9}, {%0,%1,%2,%3};"
                 : "+f"(c[0]), "+f"(c[1]), "+f"(c[2]), "+f"(c[3])
                 : "r"(a[0]), "r"(a[1]), "r"(a[2]), "r"(a[3]), "r"(b[0]), "r"(b[1]));
}
__device__ __forceinline__ void cpa16(uint32_t d, const void* s, int sz) {
    asm volatile("cp.async.cg.shared.global [%0], [%1], 16, %2;" :: "r"(d), "l"(s), "r"(sz));
}
__device__ __forceinline__ void cp_commit() { asm volatile("cp.async.commit_group;"); }
__device__ __forceinline__ void cp_wait1() { asm volatile("cp.async.wait_group 1;"); }
__device__ __forceinline__ void cp_wait0() { asm volatile("cp.async.wait_group 0;"); }

// ---------------------------------------------------------------------------
// W pre-split: [Wl|Wr] fp32 -> hi/lo fp16
__global__ void split_w(const float* __restrict__ Wl, const float* __restrict__ Wr,
                        __half* __restrict__ Wh, __half* __restrict__ Wlo) {
    int idx = blockIdx.x * 256 + threadIdx.x;
    if (idx >= WAV * GC2) return;
    int col = idx & 255, row = idx >> 8;
    float v = (col < GC) ? Wl[row * GC + col] : Wr[row * GC + (col - GC)];
    __half h = __float2half_rn(v);
    Wh[idx] = h;
    Wlo[idx] = __float2half_rn(v - __half2float(h));
}

// ---------------------------------------------------------------------------
// fp16-split tensor-core GEMM: tile 128x256, 512 thr (16 warps 4m x 4n)
#define ASTR 40                 // A smem row stride (halfs)
#define BSTR 264                // B smem row stride (halfs)
#define A_HALF (MTILE * ASTR)   // 5120 halfs per stage per half-matrix
#define B_HALF (32 * BSTR)      // 8448

__global__ void __launch_bounds__(512, 1)
gemm_tc(const float* __restrict__ X,
        const __half* __restrict__ Wh,
        const __half* __restrict__ Wlo,
        float* __restrict__ Gp) {
    extern __shared__ __half sm[];
    __half* Ah = sm;                     // [2][A_HALF]
    __half* Al = Ah + 2 * A_HALF;
    __half* Bh = Al + 2 * A_HALF;        // [2][B_HALF]
    __half* Bl = Bh + 2 * B_HALF;

    uint32_t sAh = (uint32_t)__cvta_generic_to_shared(Ah);
    uint32_t sAl = (uint32_t)__cvta_generic_to_shared(Al);
    uint32_t sBh = (uint32_t)__cvta_generic_to_shared(Bh);
    uint32_t sBl = (uint32_t)__cvta_generic_to_shared(Bl);

    int bm = blockIdx.x, s = blockIdx.y;
    int tid = threadIdx.x, lane = tid & 31, w = tid >> 5;
    int wm = w >> 2, wn = w & 3;
    int m0 = bm * MTILE;
    int k0 = s * CHUNK;

    int arow = tid >> 2, aq = (tid & 3) * 4;   // A loader: row, k-offsets aq / aq+16

    float acc[2][8][4];
#pragma unroll
    for (int mt = 0; mt < 2; mt++)
#pragma unroll
        for (int nt = 0; nt < 8; nt++)
#pragma unroll
            for (int c = 0; c < 4; c++) acc[mt][nt][c] = 0.f;

    float4 a0, a1;

    auto ldgA = [&](int st) {
        int kt = k0 + st * 32;
        const float* p = X + (size_t)(m0 + arow) * WAV + kt;
        a0 = (kt + aq + 3 < WAV) ? *(const float4*)(p + aq)
                                 : make_float4(
            (kt + aq + 0 < WAV) ? p[aq + 0] : 0.f,
            (kt + aq + 1 < WAV) ? p[aq + 1] : 0.f,
            (kt + aq + 2 < WAV) ? p[aq + 2] : 0.f,
            (kt + aq + 3 < WAV) ? p[aq + 3] : 0.f);
        a1 = (kt + aq + 19 < WAV) ? *(const float4*)(p + aq + 16)
                                  : make_float4(
            (kt + aq + 16 < WAV) ? p[aq + 16] : 0.f,
            (kt + aq + 17 < WAV) ? p[aq + 17] : 0.f,
            (kt + aq + 18 < WAV) ? p[aq + 18] : 0.f,
            (kt + aq + 19 < WAV) ? p[aq + 19] : 0.f);
    };
    auto stsA = [&](int st) {
        int base = (st & 1) * A_HALF + arow * ASTR;
#pragma unroll
        for (int hv = 0; hv < 2; hv++) {
            float4 v = hv ? a1 : a0;
            int off = base + aq + hv * 16;
            __half hx = __float2half_rn(v.x), hy = __float2half_rn(v.y);
            __half hz = __float2half_rn(v.z), hw = __float2half_rn(v.w);
            *(__half2*)(Ah + off)     = __halves2half2(hx, hy);
            *(__half2*)(Ah + off + 2) = __halves2half2(hz, hw);
            *(__half2*)(Al + off)     = __halves2half2(
                __float2half_rn(v.x - __half2float(hx)),
                __float2half_rn(v.y - __half2float(hy)));
            *(__half2*)(Al + off + 2) = __halves2half2(
                __float2half_rn(v.z - __half2float(hz)),
                __float2half_rn(v.w - __half2float(hw)));
        }
    };
    auto cpB = [&](int st) {
        int kt = k0 + st * 32;
        int sb = (st & 1) * B_HALF;
#pragma unroll
        for (int q = 0; q < 2; q++) {
            int idx = tid + q * 512;
            int row = idx >> 5, ch = (idx & 31) * 8;
            int k = kt + row;
            int sz = (k < WAV) ? 16 : 0;
            int kc = (k < WAV) ? k : (WAV - 1);
            uint32_t doff = (uint32_t)(sb + row * BSTR + ch) * 2;
            cpa16(sBh + doff, Wh + (size_t)kc * GC2 + ch, sz);
            cpa16(sBl + doff, Wlo + (size_t)kc * GC2 + ch, sz);
        }
        cp_commit();
    };
    auto compute = [&](int b) {
        uint32_t aOffH = sAh + (uint32_t)(b * A_HALF) * 2;
        uint32_t aOffL = sAl + (uint32_t)(b * A_HALF) * 2;
        uint32_t bOffH = sBh + (uint32_t)(b * B_HALF) * 2;
        uint32_t bOffL = sBl + (uint32_t)(b * B_HALF) * 2;
        int l15 = lane & 15, lhi = (lane >> 4) << 3;
#pragma unroll
        for (int k16 = 0; k16 < 32; k16 += 16) {
            uint32_t ah[2][4], al[2][4];
#pragma unroll
            for (int mt = 0; mt < 2; mt++) {
                uint32_t off = (uint32_t)((wm * 32 + mt * 16 + l15) * ASTR + k16 + lhi) * 2;
                ldsm_x4(ah[mt], aOffH + off);
                ldsm_x4(al[mt], aOffL + off);
            }
#pragma unroll
            for (int p = 0; p < 4; p++) {
                uint32_t offb = (uint32_t)((k16 + l15) * BSTR + wn * 64 + p * 16 + lhi) * 2;
                uint32_t bh[4], bl[4];
                ldsm_x4t(bh, bOffH + offb);
                ldsm_x4t(bl, bOffL + offb);
#pragma unroll
                for (int mt = 0; mt < 2; mt++) {
                    mma_f16(acc[mt][2 * p],     ah[mt], bh);
                    mma_f16(acc[mt][2 * p],     ah[mt], bl);
                    mma_f16(acc[mt][2 * p],     al[mt], bh);
                    mma_f16(acc[mt][2 * p + 1], ah[mt], bh + 2);
                    mma_f16(acc[mt][2 * p + 1], ah[mt], bl + 2);
                    mma_f16(acc[mt][2 * p + 1], al[mt], bh + 2);
                }
            }
        }
    };

    ldgA(0); stsA(0); cpB(0);
    for (int it = 0; it < NSTAGE; it++) {
        if (it + 1 < NSTAGE) { ldgA(it + 1); cpB(it + 1); }
        if (it + 1 < NSTAGE) cp_wait1(); else cp_wait0();
        __syncthreads();
        compute(it & 1);
        if (it + 1 < NSTAGE) stsA(it + 1);
        __syncthreads();
    }

    float* out = Gp + (size_t)s * N_NODES * GC2;
    int gid = lane >> 2, tig = lane & 3;
#pragma unroll
    for (int mt = 0; mt < 2; mt++) {
        int r = m0 + wm * 32 + mt * 16 + gid;
#pragma unroll
        for (int nt = 0; nt < 8; nt++) {
            int c = wn * 64 + nt * 8 + tig * 2;
            *(float2*)&out[(size_t)r * GC2 + c] =
                make_float2(acc[mt][nt][0], acc[mt][nt][1]);
            *(float2*)&out[(size_t)(r + 8) * GC2 + c] =
                make_float2(acc[mt][nt][2], acc[mt][nt][3]);
        }
    }
}

__global__ void reduce_split(const float* __restrict__ Gp, float* __restrict__ G) {
    int i = blockIdx.x * 256 + threadIdx.x;
    float s = 0.f;
#pragma unroll
    for (int p = 0; p < GSPLITS; p++) s += Gp[(size_t)p * (N_NODES * GC2) + i];
    G[i] = s;
}

// ---------------------------------------------------------------------------
// cvec: cr[i,h] = sum_f a_f * g_r[i,h,f]; cl[i,h] = sum_f a_f * g_l[i,h,f]
__global__ void cvec_kernel(const float* __restrict__ G,
                            const float* __restrict__ avec,
                            float* __restrict__ cr, float* __restrict__ cl) {
    int idx = blockIdx.x * 256 + threadIdx.x;    // < 768*4*2 = 6144
    int side = idx & 1, h = (idx >> 1) & 3, i = idx >> 3;
    const float* g = G + (size_t)i * GC2 + side * GC + h * 32;
    float s = 0.f;
#pragma unroll
    for (int f = 0; f < 32; f += 4) {
        float4 gv = *(const float4*)(g + f);
        float4 av = *(const float4*)(avec + f);
        s += gv.x * av.x + gv.y * av.y + gv.z * av.z + gv.w * av.w;
    }
    (side ? cr : cl)[i * NH + h] = s;
}

// ---------------------------------------------------------------------------
// e[i,j,h] = 0.6*(cr[i,h]+cl[j,h]) + sum_f (0.4 a_f)*|gr[i,h,f]+gl[j,h,f]|
__global__ void e_kernel(const float* __restrict__ G,
                         const int* __restrict__ adj,
                         const float* __restrict__ avec,
                         const float* __restrict__ cr,
                         const float* __restrict__ cl,
                         float* __restrict__ es) {
    __shared__ float grs[32][33];
    __shared__ float gls[64][33];
    __shared__ float asm_[32];
    __shared__ float crs[32][NH];
    __shared__ float cls[64][NH];

    int i0 = blockIdx.x * 32, j0 = blockIdx.y * 64;
    int tid = threadIdx.x;
    int tj = tid & 15, ti = tid >> 4;

    if (tid < 32) asm_[tid] = 0.4f * avec[tid];
    if (tid < 128) crs[tid >> 2][tid & 3] = cr[(i0 + (tid >> 2)) * NH + (tid & 3)];
    if (tid >= 128 && tid < 128 + 256 - 128) {}   // noop
    {
        int t2 = tid;
        if (t2 < 256) {
            int r = t2 >> 2, h = t2 & 3;
            if (r < 64) cls[r][h] = cl[(j0 + r) * NH + h];
        }
    }

    int adjv[2][4];
#pragma unroll
    for (int r = 0; r < 2; r++)
#pragma unroll
        for (int q = 0; q < 4; q++)
            adjv[r][q] = adj[(size_t)(i0 + ti * 2 + r) * N_NODES + j0 + tj + 16 * q];

    for (int h = 0; h < NH; h++) {
        __syncthreads();
        {
            int r = tid >> 3, fq = (tid & 7) * 4;
            float4 v = *(const float4*)(G + (size_t)(i0 + r) * GC2 + GC + h * 32 + fq);
            grs[r][fq + 0] = v.x; grs[r][fq + 1] = v.y;
            grs[r][fq + 2] = v.z; grs[r][fq + 3] = v.w;
        }
#pragma unroll
        for (int e2 = 0; e2 < 2; e2++) {
            int slot = tid + e2 * 256;
            int r = slot >> 3, fq = (slot & 7) * 4;
            float4 v = *(const float4*)(G + (size_t)(j0 + r) * GC2 + h * 32 + fq);
            gls[r][fq + 0] = v.x; gls[r][fq + 1] = v.y;
            gls[r][fq + 2] = v.z; gls[r][fq + 3] = v.w;
        }
        __syncthreads();

        float acc[2][4];
#pragma unroll
        for (int r = 0; r < 2; r++)
#pragma unroll
            for (int q = 0; q < 4; q++) acc[r][q] = 0.f;

#pragma unroll
        for (int f = 0; f < 32; f++) {
            float av = asm_[f];
            float gr0 = grs[ti * 2][f];
            float gr1 = grs[ti * 2 + 1][f];
            float gl[4];
#pragma unroll
            for (int q = 0; q < 4; q++) gl[q] = gls[tj + 16 * q][f];
#pragma unroll
            for (int q = 0; q < 4; q++) {
                acc[0][q] = fmaf(av, fabsf(gr0 + gl[q]), acc[0][q]);
                acc[1][q] = fmaf(av, fabsf(gr1 + gl[q]), acc[1][q]);
            }
        }

        float* ep = es + (size_t)h * N_NODES * N_NODES;
#pragma unroll
        for (int r = 0; r < 2; r++) {
            float crv = crs[ti * 2 + r][h];
            float* row = ep + (size_t)(i0 + ti * 2 + r) * N_NODES + j0;
#pragma unroll
            for (int q = 0; q < 4; q++) {
                float e = fmaf(0.6f, crv + cls[tj + 16 * q][h], acc[r][q]);
                row[tj + 16 * q] = adjv[r][q] ? e : -1e30f;
            }
        }
    }
}

// ---------------------------------------------------------------------------
// softmax over j per (i,h); 256 threads, 2 warps per head.
__global__ void attw_kernel(const float* __restrict__ es,
                            float* __restrict__ attO) {
    __shared__ float pbuf[N_NODES * NH];
    __shared__ float wmax[8];
    __shared__ float wsum[8];
    int i = blockIdx.x;
    int tid = threadIdx.x;
    int lane = tid & 31, w = tid >> 5;
    int h = w >> 1, half = w & 1;

    const float* ep = es + ((size_t)h * N_NODES + i) * N_NODES + half * 384;
    float ev[12];
    float m = -1e30f;
#pragma unroll
    for (int k = 0; k < 12; k++) {
        ev[k] = ep[lane + 32 * k];
        m = fmaxf(m, ev[k]);
    }
#pragma unroll
    for (int o = 16; o > 0; o >>= 1)
        m = fmaxf(m, __shfl_xor_sync(0xffffffffu, m, o));
    if (lane == 0) wmax[w] = m;
    __syncthreads();
    float M = fmaxf(wmax[h * 2], wmax[h * 2 + 1]);

    float ss = 0.f;
#pragma unroll
    for (int k = 0; k < 12; k++) {
        ev[k] = expf(ev[k] - M);
        ss += ev[k];
    }
#pragma unroll
    for (int o = 16; o > 0; o >>= 1)
        ss += __shfl_xor_sync(0xffffffffu, ss, o);
    if (lane == 0) wsum[w] = ss;
    __syncthreads();
    float inv = 1.f / (wsum[h * 2] + wsum[h * 2 + 1]);

#pragma unroll
    for (int k = 0; k < 12; k++)
        pbuf[(half * 384 + lane + 32 * k) * NH + h] = ev[k] * inv;
    __syncthreads();

    float4* dst = (float4*)(attO + (size_t)i * N_NODES * NH);
    const float4* src = (const float4*)pbuf;
    for (int j = tid; j < N_NODES; j += 256) dst[j] = src[j];
}

// ---------------------------------------------------------------------------
// res: z[i,f] = 0.25 * sum_{j,h} att[i,j,h] * g_r[j,h,f]; 2-way j split
#define RT 6
__global__ void res_kernel(const float* __restrict__ G,
                           const float* __restrict__ attO,
                           float* __restrict__ outv, int doElu) {
    __shared__ float atts[2][RT][512];
    __shared__ float accsm[2][RT][GC];
    int i0 = blockIdx.x * RT;
    int tid = threadIdx.x;
    int half = tid >> 7, t = tid & 127;
    int h = t >> 5;

    float acc[RT];
#pragma unroll
    for (int it = 0; it < RT; it++) acc[it] = 0.f;

    for (int c = 0; c < 3; c++) {
        __syncthreads();
#pragma unroll
        for (int it = 0; it < RT; it++) {
            float4 v = *(const float4*)(attO + (size_t)(i0 + it) * (N_NODES * NH)
                                        + half * 1536 + c * 512 + t * 4);
            *(float4*)&atts[half][it][t * 4] = v;
        }
        __syncthreads();
#pragma unroll 4
        for (int jj = 0; jj < 128; jj++) {
            int j = half * 384 + c * 128 + jj;
            float g = G[(size_t)j * GC2 + GC + t];
#pragma unroll
            for (int it = 0; it < RT; it++)
                acc[it] = fmaf(atts[half][it][jj * NH + h], g, acc[it]);
        }
    }
#pragma unroll
    for (int it = 0; it < RT; it++) accsm[half][it][t] = acc[it];
    __syncthreads();

    if (tid < RT * 32) {
        int it = tid >> 5, f = tid & 31;
        float m = 0.f;
#pragma unroll
        for (int hh = 0; hh < 2; hh++)
#pragma unroll
            for (int q = 0; q < 4; q++)
                m += accsm[hh][it][q * 32 + f];
        m *= 0.25f;
        if (doElu) m = (m > 0.f) ? m : expm1f(m);
        outv[(size_t)(i0 + it) * HID + f] = m;
    }
}

// ---------------------------------------------------------------------------
__global__ void mapper_kernel(const float* __restrict__ z,
                              const float* __restrict__ Wm,
                              const float* __restrict__ bm,
                              float* __restrict__ staO,
                              float* __restrict__ zh) {
    __shared__ float ws[SUP * SUP];
    int p = blockIdx.x;
    int tid = threadIdx.x;
    for (int idx = tid; idx < SUP * SUP; idx += 256)
        ws[idx] = Wm[(size_t)p * SUP * SUP + idx];
    __syncthreads();

    for (int idx = tid; idx < SUP * HID; idx += 256) {
        int t = idx & 31, e = idx >> 5;
        float s = bm[p * SUP + e];
#pragma unroll 4
        for (int d = 0; d < SUP; d++)
            s = fmaf(z[(size_t)(p * SUP + d) * HID + t], ws[d * SUP + e], s);
        staO[(size_t)t * N_NODES + p * SUP + e] = s;
        zh[(size_t)(p * SUP + e) * HID + t] = s;
    }
}

__global__ void gemm_small(const float* __restrict__ zh,
                           const float* __restrict__ Wl,
                           const float* __restrict__ Wr,
                           float* __restrict__ G) {
    __shared__ float zr[HID];
    int i = blockIdx.x;
    int c = threadIdx.x;
    if (c < HID) zr[c] = zh[(size_t)i * HID + c];
    __syncthreads();
    const float* W = (c < GC) ? Wl : Wr;
    int cc = c & 127;
    float s = 0.f;
#pragma unroll
    for (int k = 0; k < HID; k++) s = fmaf(zr[k], W[k * GC + cc], s);
    G[(size_t)i * GC2 + c] = s;
}

// ---------------------------------------------------------------------------
extern "C" void kernel_launch(void* const* d_in, const int* in_sizes, int n_in,
                              void* d_out, int out_size) {
    const float* x    = (const float*)d_in[0];
    const float* Wl1  = (const float*)d_in[1];
    const float* Wr1  = (const float*)d_in[2];
    const float* a1   = (const float*)d_in[3];
    const float* Wm   = (const float*)d_in[4];
    const float* bm   = (const float*)d_in[5];
    const float* Wl2  = (const float*)d_in[6];
    const float* Wr2  = (const float*)d_in[7];
    const float* a2   = (const float*)d_in[8];
    const int*   adjS = (const int*)d_in[9];
    const int*   adjT = (const int*)d_in[10];

    float* out  = (float*)d_out;                           // [768,32]
    float* attS = out + N_NODES * HID;                     // [768,768,4]
    float* attT = attS + (size_t)N_NODES * N_NODES * NH;
    float* staO = attT + (size_t)N_NODES * N_NODES * NH;   // [32,768]

    float *gp, *g1, *g2, *z1, *zh, *es, *crp, *clp;
    __half *wh, *wlo;
    cudaGetSymbolAddress((void**)&gp, d_Gp);
    cudaGetSymbolAddress((void**)&g1, d_G1);
    cudaGetSymbolAddress((void**)&g2, d_G2);
    cudaGetSymbolAddress((void**)&z1, d_z1);
    cudaGetSymbolAddress((void**)&zh, d_zh);
    cudaGetSymbolAddress((void**)&es, d_es);
    cudaGetSymbolAddress((void**)&crp, d_cr);
    cudaGetSymbolAddress((void**)&clp, d_cl);
    cudaGetSymbolAddress((void**)&wh, d_Wh);
    cudaGetSymbolAddress((void**)&wlo, d_Wlo);

    const int SMEM_GEMM = (2 * A_HALF * 2 + 2 * B_HALF * 2) * 2;   // 108544
    cudaFuncSetAttribute(gemm_tc, cudaFuncAttributeMaxDynamicSharedMemorySize,
                         SMEM_GEMM);

    // layer 1
    split_w<<<(WAV * GC2 + 255) / 256, 256>>>(Wl1, Wr1, wh, wlo);
    gemm_tc<<<dim3(N_NODES / MTILE, GSPLITS), 512, SMEM_GEMM>>>(x, wh, wlo, gp);
    reduce_split<<<N_NODES * GC2 / 256, 256>>>(gp, g1);
    cvec_kernel<<<N_NODES * NH * 2 / 256, 256>>>(g1, a1, crp, clp);
    e_kernel<<<dim3(N_NODES / 32, N_NODES / 64), 256>>>(g1, adjS, a1, crp, clp, es);
    attw_kernel<<<N_NODES, 256>>>(es, attS);
    res_kernel<<<N_NODES / RT, 256>>>(g1, attS, z1, 1);

    // mapper
    mapper_kernel<<<P_PATCH, 256>>>(z1, Wm, bm, staO, zh);

    // layer 2
    gemm_small<<<N_NODES, 256>>>(zh, Wl2, Wr2, g2);
    cvec_kernel<<<N_NODES * NH * 2 / 256, 256>>>(g2, a2, crp, clp);
    e_kernel<<<dim3(N_NODES / 32, N_NODES / 64), 256>>>(g2, adjT, a2, crp, clp, es);
    attw_kernel<<<N_NODES, 256>>>(es, attT);
    res_kernel<<<N_NODES / RT, 256>>>(g2, attT, out, 0);
}

// round 8
// speedup vs baseline: 1.4014x; 1.2178x over previous
#include <cuda_runtime.h>
#include <cuda_fp16.h>
#include <math.h>
#include <stdint.h>

#define N_NODES 768
#define WAV 6360
#define HID 32
#define NH 4
#define GC 128          // H*HID
#define GC2 256         // [g_l | g_r]
#define P_PATCH 8
#define SUP 96
#define NEG 0.2f

#define GSPLITS 24
#define CHUNK 288
#define NSTAGE 9
#define MTILE 128

// device scratch (no allocation allowed)
__device__ float  d_Gp[GSPLITS * N_NODES * GC2];
__device__ float  d_G1[N_NODES * GC2];
__device__ float  d_G2[N_NODES * GC2];
__device__ float  d_z1[N_NODES * HID];
__device__ float  d_zh[N_NODES * HID];
__device__ float  d_es[NH * N_NODES * N_NODES];   // e scores [h][i][j]
__device__ __half d_Wh[WAV * GC2];
__device__ __half d_Wlo[WAV * GC2];

// ---------------------------------------------------------------------------
__device__ __forceinline__ void ldsm_x4(uint32_t* r, uint32_t a) {
    asm volatile("ldmatrix.sync.aligned.m8n8.x4.shared.b16 {%0,%1,%2,%3}, [%4];"
                 : "=r"(r[0]), "=r"(r[1]), "=r"(r[2]), "=r"(r[3]) : "r"(a));
}
__device__ __forceinline__ void ldsm_x4t(uint32_t* r, uint32_t a) {
    asm volatile("ldmatrix.sync.aligned.m8n8.x4.trans.shared.b16 {%0,%1,%2,%3}, [%4];"
                 : "=r"(r[0]), "=r"(r[1]), "=r"(r[2]), "=r"(r[3]) : "r"(a));
}
__device__ __forceinline__ void mma_f16(float* c, const uint32_t* a, const uint32_t* b) {
    asm volatile("mma.sync.aligned.m16n8k16.row.col.f32.f16.f16.f32 "
                 "{%0,%1,%2,%3}, {%4,%5,%6,%7}, {%8,%9}, {%0,%1,%2,%3};"
                 : "+f"(c[0]), "+f"(c[1]), "+f"(c[2]), "+f"(c[3])
                 : "r"(a[0]), "r"(a[1]), "r"(a[2]), "r"(a[3]), "r"(b[0]), "r"(b[1]));
}
__device__ __forceinline__ void cpa16(uint32_t d, const void* s, int sz) {
    asm volatile("cp.async.cg.shared.global [%0], [%1], 16, %2;" :: "r"(d), "l"(s), "r"(sz));
}
__device__ __forceinline__ void cp_commit() { asm volatile("cp.async.commit_group;"); }
__device__ __forceinline__ void cp_wait1() { asm volatile("cp.async.wait_group 1;"); }
__device__ __forceinline__ void cp_wait0() { asm volatile("cp.async.wait_group 0;"); }

// ---------------------------------------------------------------------------
__global__ void split_w(const float* __restrict__ Wl, const float* __restrict__ Wr,
                        __half* __restrict__ Wh, __half* __restrict__ Wlo) {
    int idx = blockIdx.x * 256 + threadIdx.x;
    if (idx >= WAV * GC2) return;
    int col = idx & 255, row = idx >> 8;
    float v = (col < GC) ? Wl[row * GC + col] : Wr[row * GC + (col - GC)];
    __half h = __float2half_rn(v);
    Wh[idx] = h;
    Wlo[idx] = __float2half_rn(v - __half2float(h));
}

// ---------------------------------------------------------------------------
// fp16-split tensor-core GEMM: tile 128x256, 512 thr (16 warps 4m x 4n)
#define ASTR 40
#define BSTR 264
#define A_HALF (MTILE * ASTR)
#define B_HALF (32 * BSTR)

__global__ void __launch_bounds__(512, 1)
gemm_tc(const float* __restrict__ X,
        const __half* __restrict__ Wh,
        const __half* __restrict__ Wlo,
        float* __restrict__ Gp) {
    extern __shared__ __half sm[];
    __half* Ah = sm;
    __half* Al = Ah + 2 * A_HALF;
    __half* Bh = Al + 2 * A_HALF;
    __half* Bl = Bh + 2 * B_HALF;

    uint32_t sAh = (uint32_t)__cvta_generic_to_shared(Ah);
    uint32_t sAl = (uint32_t)__cvta_generic_to_shared(Al);
    uint32_t sBh = (uint32_t)__cvta_generic_to_shared(Bh);
    uint32_t sBl = (uint32_t)__cvta_generic_to_shared(Bl);

    int bm = blockIdx.x, s = blockIdx.y;
    int tid = threadIdx.x, lane = tid & 31, w = tid >> 5;
    int wm = w >> 2, wn = w & 3;
    int m0 = bm * MTILE;
    int k0 = s * CHUNK;

    int arow = tid >> 2, aq = (tid & 3) * 4;

    float acc[2][8][4];
#pragma unroll
    for (int mt = 0; mt < 2; mt++)
#pragma unroll
        for (int nt = 0; nt < 8; nt++)
#pragma unroll
            for (int c = 0; c < 4; c++) acc[mt][nt][c] = 0.f;

    float4 a0, a1;

    auto ldgA = [&](int st) {
        int kt = k0 + st * 32;
        const float* p = X + (size_t)(m0 + arow) * WAV + kt;
        a0 = (kt + aq + 3 < WAV) ? *(const float4*)(p + aq)
                                 : make_float4(
            (kt + aq + 0 < WAV) ? p[aq + 0] : 0.f,
            (kt + aq + 1 < WAV) ? p[aq + 1] : 0.f,
            (kt + aq + 2 < WAV) ? p[aq + 2] : 0.f,
            (kt + aq + 3 < WAV) ? p[aq + 3] : 0.f);
        a1 = (kt + aq + 19 < WAV) ? *(const float4*)(p + aq + 16)
                                  : make_float4(
            (kt + aq + 16 < WAV) ? p[aq + 16] : 0.f,
            (kt + aq + 17 < WAV) ? p[aq + 17] : 0.f,
            (kt + aq + 18 < WAV) ? p[aq + 18] : 0.f,
            (kt + aq + 19 < WAV) ? p[aq + 19] : 0.f);
    };
    auto stsA = [&](int st) {
        int base = (st & 1) * A_HALF + arow * ASTR;
#pragma unroll
        for (int hv = 0; hv < 2; hv++) {
            float4 v = hv ? a1 : a0;
            int off = base + aq + hv * 16;
            __half hx = __float2half_rn(v.x), hy = __float2half_rn(v.y);
            __half hz = __float2half_rn(v.z), hw = __float2half_rn(v.w);
            *(__half2*)(Ah + off)     = __halves2half2(hx, hy);
            *(__half2*)(Ah + off + 2) = __halves2half2(hz, hw);
            *(__half2*)(Al + off)     = __halves2half2(
                __float2half_rn(v.x - __half2float(hx)),
                __float2half_rn(v.y - __half2float(hy)));
            *(__half2*)(Al + off + 2) = __halves2half2(
                __float2half_rn(v.z - __half2float(hz)),
                __float2half_rn(v.w - __half2float(hw)));
        }
    };
    auto cpB = [&](int st) {
        int kt = k0 + st * 32;
        int sb = (st & 1) * B_HALF;
#pragma unroll
        for (int q = 0; q < 2; q++) {
            int idx = tid + q * 512;
            int row = idx >> 5, ch = (idx & 31) * 8;
            int k = kt + row;
            int sz = (k < WAV) ? 16 : 0;
            int kc = (k < WAV) ? k : (WAV - 1);
            uint32_t doff = (uint32_t)(sb + row * BSTR + ch) * 2;
            cpa16(sBh + doff, Wh + (size_t)kc * GC2 + ch, sz);
            cpa16(sBl + doff, Wlo + (size_t)kc * GC2 + ch, sz);
        }
        cp_commit();
    };
    auto compute = [&](int b) {
        uint32_t aOffH = sAh + (uint32_t)(b * A_HALF) * 2;
        uint32_t aOffL = sAl + (uint32_t)(b * A_HALF) * 2;
        uint32_t bOffH = sBh + (uint32_t)(b * B_HALF) * 2;
        uint32_t bOffL = sBl + (uint32_t)(b * B_HALF) * 2;
        int l15 = lane & 15, lhi = (lane >> 4) << 3;
#pragma unroll
        for (int k16 = 0; k16 < 32; k16 += 16) {
            uint32_t ah[2][4], al[2][4];
#pragma unroll
            for (int mt = 0; mt < 2; mt++) {
                uint32_t off = (uint32_t)((wm * 32 + mt * 16 + l15) * ASTR + k16 + lhi) * 2;
                ldsm_x4(ah[mt], aOffH + off);
                ldsm_x4(al[mt], aOffL + off);
            }
#pragma unroll
            for (int p = 0; p < 4; p++) {
                uint32_t offb = (uint32_t)((k16 + l15) * BSTR + wn * 64 + p * 16 + lhi) * 2;
                uint32_t bh[4], bl[4];
                ldsm_x4t(bh, bOffH + offb);
                ldsm_x4t(bl, bOffL + offb);
#pragma unroll
                for (int mt = 0; mt < 2; mt++) {
                    mma_f16(acc[mt][2 * p],     ah[mt], bh);
                    mma_f16(acc[mt][2 * p],     ah[mt], bl);
                    mma_f16(acc[mt][2 * p],     al[mt], bh);
                    mma_f16(acc[mt][2 * p + 1], ah[mt], bh + 2);
                    mma_f16(acc[mt][2 * p + 1], ah[mt], bl + 2);
                    mma_f16(acc[mt][2 * p + 1], al[mt], bh + 2);
                }
            }
        }
    };

    ldgA(0); stsA(0); cpB(0);
    for (int it = 0; it < NSTAGE; it++) {
        if (it + 1 < NSTAGE) { ldgA(it + 1); cpB(it + 1); }
        if (it + 1 < NSTAGE) cp_wait1(); else cp_wait0();
        __syncthreads();
        compute(it & 1);
        if (it + 1 < NSTAGE) stsA(it + 1);
        __syncthreads();
    }

    float* out = Gp + (size_t)s * N_NODES * GC2;
    int gid = lane >> 2, tig = lane & 3;
#pragma unroll
    for (int mt = 0; mt < 2; mt++) {
        int r = m0 + wm * 32 + mt * 16 + gid;
#pragma unroll
        for (int nt = 0; nt < 8; nt++) {
            int c = wn * 64 + nt * 8 + tig * 2;
            *(float2*)&out[(size_t)r * GC2 + c] =
                make_float2(acc[mt][nt][0], acc[mt][nt][1]);
            *(float2*)&out[(size_t)(r + 8) * GC2 + c] =
                make_float2(acc[mt][nt][2], acc[mt][nt][3]);
        }
    }
}

__global__ void reduce_split(const float* __restrict__ Gp, float* __restrict__ G) {
    int i = blockIdx.x * 256 + threadIdx.x;
    float s = 0.f;
#pragma unroll
    for (int p = 0; p < GSPLITS; p++) s += Gp[(size_t)p * (N_NODES * GC2) + i];
    G[i] = s;
}

// ---------------------------------------------------------------------------
// e[i,j,h] = 1.5*(pr[i,h]+pl[j,h]) + sum_f (0.4 a_f)*|gr+gl|  (cvec fused)
__global__ void e_kernel(const float* __restrict__ G,
                         const int* __restrict__ adj,
                         const float* __restrict__ avec,
                         float* __restrict__ es) {
    __shared__ float grs[32][33];
    __shared__ float gls[64][33];
    __shared__ float asm_[32];
    __shared__ float prs[32];
    __shared__ float pls[64];

    int i0 = blockIdx.x * 32, j0 = blockIdx.y * 64;
    int tid = threadIdx.x;
    int tj = tid & 15, ti = tid >> 4;

    if (tid < 32) asm_[tid] = 0.4f * avec[tid];

    int adjv[2][4];
#pragma unroll
    for (int r = 0; r < 2; r++)
#pragma unroll
        for (int q = 0; q < 4; q++)
            adjv[r][q] = adj[(size_t)(i0 + ti * 2 + r) * N_NODES + j0 + tj + 16 * q];

    for (int h = 0; h < NH; h++) {
        __syncthreads();
        {
            int r = tid >> 3, fq = (tid & 7) * 4;
            float4 v = *(const float4*)(G + (size_t)(i0 + r) * GC2 + GC + h * 32 + fq);
            grs[r][fq + 0] = v.x; grs[r][fq + 1] = v.y;
            grs[r][fq + 2] = v.z; grs[r][fq + 3] = v.w;
        }
#pragma unroll
        for (int e2 = 0; e2 < 2; e2++) {
            int slot = tid + e2 * 256;
            int r = slot >> 3, fq = (slot & 7) * 4;
            float4 v = *(const float4*)(G + (size_t)(j0 + r) * GC2 + h * 32 + fq);
            gls[r][fq + 0] = v.x; gls[r][fq + 1] = v.y;
            gls[r][fq + 2] = v.z; gls[r][fq + 3] = v.w;
        }
        __syncthreads();

        // fused cvec partials: pr (threads 0..31), pl (threads 32..95)
        if (tid < 32) {
            float s = 0.f;
#pragma unroll
            for (int f = 0; f < 32; f++) s = fmaf(asm_[f], grs[tid][f], s);
            prs[tid] = s;
        } else if (tid < 96) {
            int j = tid - 32;
            float s = 0.f;
#pragma unroll
            for (int f = 0; f < 32; f++) s = fmaf(asm_[f], gls[j][f], s);
            pls[j] = s;
        }

        float acc[2][4];
#pragma unroll
        for (int r = 0; r < 2; r++)
#pragma unroll
            for (int q = 0; q < 4; q++) acc[r][q] = 0.f;

#pragma unroll
        for (int f = 0; f < 32; f++) {
            float av = asm_[f];
            float gr0 = grs[ti * 2][f];
            float gr1 = grs[ti * 2 + 1][f];
            float gl[4];
#pragma unroll
            for (int q = 0; q < 4; q++) gl[q] = gls[tj + 16 * q][f];
#pragma unroll
            for (int q = 0; q < 4; q++) {
                acc[0][q] = fmaf(av, fabsf(gr0 + gl[q]), acc[0][q]);
                acc[1][q] = fmaf(av, fabsf(gr1 + gl[q]), acc[1][q]);
            }
        }
        __syncthreads();

        float* ep = es + (size_t)h * N_NODES * N_NODES;
#pragma unroll
        for (int r = 0; r < 2; r++) {
            float prv = prs[ti * 2 + r];
            float* row = ep + (size_t)(i0 + ti * 2 + r) * N_NODES + j0;
#pragma unroll
            for (int q = 0; q < 4; q++) {
                float e = fmaf(1.5f, prv + pls[tj + 16 * q], acc[r][q]);
                row[tj + 16 * q] = adjv[r][q] ? e : -1e30f;
            }
        }
    }
}

// ---------------------------------------------------------------------------
// fused softmax + att write + res: block = IT i-rows.
#define IT 6
#define SM_SOFT (IT * NH * N_NODES * 4 + 2 * IT * GC * 4)   // 73728 + 6144

__global__ void __launch_bounds__(256)
softres_kernel(const float* __restrict__ es, const float* __restrict__ G,
               float* __restrict__ attO, float* __restrict__ outv, int doElu) {
    extern __shared__ float smf[];
    float* ebuf = smf;                           // [IT][NH][768]
    float* accsm = smf + IT * NH * N_NODES;      // [2][IT][GC]

    int i0 = blockIdx.x * IT;
    int tid = threadIdx.x, lane = tid & 31, w = tid >> 5;

    // phase 1: load es rows
#pragma unroll
    for (int combo = 0; combo < IT * NH; combo++) {
        int it = combo >> 2, h = combo & 3;
        if (tid < 192) {
            const float* src = es + ((size_t)h * N_NODES + i0 + it) * N_NODES;
            *(float4*)&ebuf[(it * NH + h) * N_NODES + tid * 4] =
                *(const float4*)(src + tid * 4);
        }
    }
    __syncthreads();

    // phase 2: softmax per (it,h); warp w handles 3 combos
#pragma unroll
    for (int cc = 0; cc < 3; cc++) {
        int combo = w * 3 + cc;
        float* row = &ebuf[combo * N_NODES];
        float ev[24];
        float m = -1e30f;
#pragma unroll
        for (int k = 0; k < 24; k++) {
            ev[k] = row[lane + 32 * k];
            m = fmaxf(m, ev[k]);
        }
#pragma unroll
        for (int o = 16; o > 0; o >>= 1)
            m = fmaxf(m, __shfl_xor_sync(0xffffffffu, m, o));
        float ss = 0.f;
#pragma unroll
        for (int k = 0; k < 24; k++) {
            ev[k] = expf(ev[k] - m);
            ss += ev[k];
        }
#pragma unroll
        for (int o = 16; o > 0; o >>= 1)
            ss += __shfl_xor_sync(0xffffffffu, ss, o);
        float inv = 1.f / ss;
#pragma unroll
        for (int k = 0; k < 24; k++)
            row[lane + 32 * k] = ev[k] * inv;
    }
    __syncthreads();

    // phase 2.5: write att gmem [i][j][h] as float4 over h
    for (int idx = tid; idx < IT * N_NODES; idx += 256) {
        int it = idx / N_NODES, j = idx - it * N_NODES;
        float4 v = make_float4(ebuf[(it * NH + 0) * N_NODES + j],
                               ebuf[(it * NH + 1) * N_NODES + j],
                               ebuf[(it * NH + 2) * N_NODES + j],
                               ebuf[(it * NH + 3) * N_NODES + j]);
        *(float4*)(attO + ((size_t)(i0 + it) * N_NODES + j) * NH) = v;
    }

    // phase 3: res accumulation (att via broadcast LDS)
    int half = tid >> 7, t = tid & 127, h = t >> 5;
    float acc[IT];
#pragma unroll
    for (int it = 0; it < IT; it++) acc[it] = 0.f;

#pragma unroll 4
    for (int jj = 0; jj < 384; jj++) {
        int j = half * 384 + jj;
        float g = G[(size_t)j * GC2 + GC + t];
#pragma unroll
        for (int it = 0; it < IT; it++)
            acc[it] = fmaf(ebuf[(it * NH + h) * N_NODES + j], g, acc[it]);
    }
#pragma unroll
    for (int it = 0; it < IT; it++)
        accsm[(half * IT + it) * GC + t] = acc[it];
    __syncthreads();

    if (tid < IT * 32) {
        int it = tid >> 5, f = tid & 31;
        float m = 0.f;
#pragma unroll
        for (int hh = 0; hh < 2; hh++)
#pragma unroll
            for (int q = 0; q < 4; q++)
                m += accsm[(hh * IT + it) * GC + q * 32 + f];
        m *= 0.25f;
        if (doElu) m = (m > 0.f) ? m : expm1f(m);
        outv[(size_t)(i0 + it) * HID + f] = m;
    }
}

// ---------------------------------------------------------------------------
__global__ void mapper_kernel(const float* __restrict__ z,
                              const float* __restrict__ Wm,
                              const float* __restrict__ bm,
                              float* __restrict__ staO,
                              float* __restrict__ zh) {
    __shared__ float ws[SUP * SUP];
    int p = blockIdx.x;
    int tid = threadIdx.x;
    for (int idx = tid; idx < SUP * SUP; idx += 256)
        ws[idx] = Wm[(size_t)p * SUP * SUP + idx];
    __syncthreads();

    for (int idx = tid; idx < SUP * HID; idx += 256) {
        int t = idx & 31, e = idx >> 5;
        float s = bm[p * SUP + e];
#pragma unroll 4
        for (int d = 0; d < SUP; d++)
            s = fmaf(z[(size_t)(p * SUP + d) * HID + t], ws[d * SUP + e], s);
        staO[(size_t)t * N_NODES + p * SUP + e] = s;
        zh[(size_t)(p * SUP + e) * HID + t] = s;
    }
}

__global__ void gemm_small(const float* __restrict__ zh,
                           const float* __restrict__ Wl,
                           const float* __restrict__ Wr,
                           float* __restrict__ G) {
    __shared__ float zr[HID];
    int i = blockIdx.x;
    int c = threadIdx.x;
    if (c < HID) zr[c] = zh[(size_t)i * HID + c];
    __syncthreads();
    const float* W = (c < GC) ? Wl : Wr;
    int cc = c & 127;
    float s = 0.f;
#pragma unroll
    for (int k = 0; k < HID; k++) s = fmaf(zr[k], W[k * GC + cc], s);
    G[(size_t)i * GC2 + c] = s;
}

// ---------------------------------------------------------------------------
extern "C" void kernel_launch(void* const* d_in, const int* in_sizes, int n_in,
                              void* d_out, int out_size) {
    const float* x    = (const float*)d_in[0];
    const float* Wl1  = (const float*)d_in[1];
    const float* Wr1  = (const float*)d_in[2];
    const float* a1   = (const float*)d_in[3];
    const float* Wm   = (const float*)d_in[4];
    const float* bm   = (const float*)d_in[5];
    const float* Wl2  = (const float*)d_in[6];
    const float* Wr2  = (const float*)d_in[7];
    const float* a2   = (const float*)d_in[8];
    const int*   adjS = (const int*)d_in[9];
    const int*   adjT = (const int*)d_in[10];

    float* out  = (float*)d_out;
    float* attS = out + N_NODES * HID;
    float* attT = attS + (size_t)N_NODES * N_NODES * NH;
    float* staO = attT + (size_t)N_NODES * N_NODES * NH;

    float *gp, *g1, *g2, *z1, *zh, *es;
    __half *wh, *wlo;
    cudaGetSymbolAddress((void**)&gp, d_Gp);
    cudaGetSymbolAddress((void**)&g1, d_G1);
    cudaGetSymbolAddress((void**)&g2, d_G2);
    cudaGetSymbolAddress((void**)&z1, d_z1);
    cudaGetSymbolAddress((void**)&zh, d_zh);
    cudaGetSymbolAddress((void**)&es, d_es);
    cudaGetSymbolAddress((void**)&wh, d_Wh);
    cudaGetSymbolAddress((void**)&wlo, d_Wlo);

    const int SMEM_GEMM = (2 * A_HALF * 2 + 2 * B_HALF * 2) * 2;
    cudaFuncSetAttribute(gemm_tc, cudaFuncAttributeMaxDynamicSharedMemorySize,
                         SMEM_GEMM);
    cudaFuncSetAttribute(softres_kernel, cudaFuncAttributeMaxDynamicSharedMemorySize,
                         SM_SOFT);

    // layer 1
    split_w<<<(WAV * GC2 + 255) / 256, 256>>>(Wl1, Wr1, wh, wlo);
    gemm_tc<<<dim3(N_NODES / MTILE, GSPLITS), 512, SMEM_GEMM>>>(x, wh, wlo, gp);
    reduce_split<<<N_NODES * GC2 / 256, 256>>>(gp, g1);
    e_kernel<<<dim3(N_NODES / 32, N_NODES / 64), 256>>>(g1, adjS, a1, es);
    softres_kernel<<<N_NODES / IT, 256, SM_SOFT>>>(es, g1, attS, z1, 1);

    // mapper
    mapper_kernel<<<P_PATCH, 256>>>(z1, Wm, bm, staO, zh);

    // layer 2
    gemm_small<<<N_NODES, 256>>>(zh, Wl2, Wr2, g2);
    e_kernel<<<dim3(N_NODES / 32, N_NODES / 64), 256>>>(g2, adjT, a2, es);
    softres_kernel<<<N_NODES / IT, 256, SM_SOFT>>>(es, g2, attT, out, 0);
}